// round 14
// baseline (speedup 1.0000x reference)
#include <cuda_runtime.h>

#define NN 100000
#define NE 600000
#define NG 512
#define FD 128
#define SCAN_B 1024
#define NB_SCAN ((NN + SCAN_B - 1) / SCAN_B)   // 98

// Scratch (allocation-free rule: __device__ globals). No float atomics anywhere.
__device__ float g_hw [NN * FD];   // h @ W
__device__ float g_agg[NN * FD];   // aggregated layer output
__device__ float g_dis[NN];        // deg^{-1/2}
__device__ int   g_deg[NN];        // in-degree (excluding self loop)
__device__ int   g_scan[NN];       // inclusive per-block scan
__device__ int   g_bsum[NB_SCAN];
__device__ int   g_boff[NB_SCAN];
__device__ int   g_rowstart[NN];   // CSR row starts (exclusive scan)
__device__ int   g_cursor[NN];     // fill cursors
__device__ int   g_csrc[NE];       // CSR: src lists grouped by dst
__device__ int   g_gstart[NG + 1]; // graph segment starts (batch is sorted)
__device__ float4 g_bfrag1[16 * 16 * 32];  // W1 mma fragments {b0h,b1h,b0l,b1l}
__device__ float4 g_bfrag2[16 * 16 * 32];  // W2 mma fragments

// ---------------------------------------------------------------------------
__global__ void k_zero() {
    int i = blockIdx.x * blockDim.x + threadIdx.x;
    if (i < NN) g_deg[i] = 0;
}

__global__ void k_count(const int* __restrict__ ei) {
    int e = blockIdx.x * blockDim.x + threadIdx.x;
    if (e < NE) atomicAdd(&g_deg[ei[NE + e]], 1);
}

__global__ void __launch_bounds__(SCAN_B) k_scan1() {
    __shared__ int s[SCAN_B];
    int tid = threadIdx.x;
    int i = blockIdx.x * SCAN_B + tid;
    s[tid] = (i < NN) ? g_deg[i] : 0;
    __syncthreads();
#pragma unroll
    for (int off = 1; off < SCAN_B; off <<= 1) {
        int v = (tid >= off) ? s[tid - off] : 0;
        __syncthreads();
        s[tid] += v;
        __syncthreads();
    }
    if (i < NN) g_scan[i] = s[tid];
    if (tid == SCAN_B - 1) g_bsum[blockIdx.x] = s[tid];
}

__global__ void __launch_bounds__(128) k_scan2() {
    __shared__ int s[128];
    int t = threadIdx.x;
    int v = (t < NB_SCAN) ? g_bsum[t] : 0;
    s[t] = v;
    __syncthreads();
#pragma unroll
    for (int off = 1; off < 128; off <<= 1) {
        int u = (t >= off) ? s[t - off] : 0;
        __syncthreads();
        s[t] += u;
        __syncthreads();
    }
    if (t < NB_SCAN) g_boff[t] = s[t] - v;   // exclusive
}

__global__ void k_scan3() {
    int i = blockIdx.x * blockDim.x + threadIdx.x;
    if (i < NN) {
        int excl = g_scan[i] + g_boff[i >> 10] - g_deg[i];
        g_rowstart[i] = excl;
        g_cursor[i]   = excl;
        g_dis[i] = rsqrtf(1.0f + (float)g_deg[i]);
    }
}

__global__ void k_fill(const int* __restrict__ ei) {
    int e = blockIdx.x * blockDim.x + threadIdx.x;
    if (e < NE) {
        int s = ei[e];
        int d = ei[NE + e];
        int pos = atomicAdd(&g_cursor[d], 1);
        g_csrc[pos] = s;
    }
}

__global__ void k_gstart(const int* __restrict__ batch) {
    int i = blockIdx.x * blockDim.x + threadIdx.x;
    if (i <= NN) {
        int prev = (i == 0) ? -1 : batch[i - 1];
        int cur  = (i < NN) ? batch[i] : NG;
        for (int g = prev + 1; g <= cur; g++) g_gstart[g] = i;
    }
}

// ---------------------------------------------------------------------------
__device__ __forceinline__ float tf32_hi(float a) {
    return __uint_as_float(__float_as_uint(a) & 0xffffe000u);
}

// Precompute W mma fragments (one-time, shared by all GEMM blocks).
// Layout: [ks(16)][nt(16)][lane(32)] float4 = {b0hi, b1hi, b0lo, b1lo}
// lane(g,t): b0 = W[ks*8+t][nt*8+g], b1 = W[ks*8+t+4][nt*8+g]
__global__ void k_bfrag(const float* __restrict__ W, float4* __restrict__ out) {
    int i = blockIdx.x * blockDim.x + threadIdx.x;
    if (i >= 16 * 16 * 32) return;
    int lane = i & 31, nt = (i >> 5) & 15, ks = i >> 9;
    int g = lane >> 2, t = lane & 3;
    int n = nt * 8 + g;
    float b0 = W[(ks * 8 + t) * FD + n];
    float b1 = W[(ks * 8 + t + 4) * FD + n];
    float b0h = tf32_hi(b0), b1h = tf32_hi(b1);
    out[i] = make_float4(b0h, b1h, b0 - b0h, b1 - b1h);
}

__device__ __forceinline__ void mma_tf32(float4& d, float a0, float a1, float a2,
                                         float a3, float b0, float b1) {
    asm volatile(
        "mma.sync.aligned.m16n8k8.row.col.f32.tf32.tf32.f32 "
        "{%0,%1,%2,%3}, {%4,%5,%6,%7}, {%8,%9}, {%0,%1,%2,%3};\n"
        : "+f"(d.x), "+f"(d.y), "+f"(d.z), "+f"(d.w)
        : "r"(__float_as_uint(a0)), "r"(__float_as_uint(a1)),
          "r"(__float_as_uint(a2)), "r"(__float_as_uint(a3)),
          "r"(__float_as_uint(b0)), "r"(__float_as_uint(b1)));
}

// Tensor-core GEMM: Out[NN,128] = f(A)[NN,128] @ W[128,128], split-TF32.
// Block 128 rows x 64 cols (gridDim.y=2 col halves), 256 threads, 3 blocks/SM.
// Warp = ONE m16 stripe x 64 cols (8 n8 tiles): accs 32 regs -> high occupancy.
// A in smem row-major stride 68 (conflict-free frag LDS); hi/lo split in regs.
// B fragments streamed from precomputed global (coalesced LDG.128, L2-hot).
template <bool RELU_BIAS>
__global__ void __launch_bounds__(256, 3) k_gemm(
    const float* __restrict__ A, const float* __restrict__ bias,
    float* __restrict__ Out, const float4* __restrict__ Bfrag)
{
    __shared__ float sA[128 * 68];  // [row][k-chunk 64 + 4 pad]

    const int block_row = blockIdx.x * 128;
    const int col_base  = blockIdx.y * 64;
    const int tid  = threadIdx.x;
    const int lane = tid & 31;
    const int w    = tid >> 5;      // 0..7 : one m16 stripe each
    const int g    = lane >> 2, t = lane & 3;

    float4 acc[8];
#pragma unroll
    for (int i = 0; i < 8; i++) acc[i] = make_float4(0.f, 0.f, 0.f, 0.f);

    for (int chunk = 0; chunk < 2; chunk++) {
        const int k0c = chunk * 64;
        // stage A (128 rows x 64 k) row-major: coalesced LDG.128 -> STS.128
        for (int idx = tid; idx < 2048; idx += 256) {
            int r = idx >> 4, q = idx & 15;
            int row = block_row + r;
            float4 v = make_float4(0.f, 0.f, 0.f, 0.f);
            if (row < NN)
                v = *reinterpret_cast<const float4*>(&A[row * FD + k0c + q * 4]);
            if (RELU_BIAS) {
                float4 bb = *reinterpret_cast<const float4*>(&bias[k0c + q * 4]);
                v.x = fmaxf(v.x + bb.x, 0.f); v.y = fmaxf(v.y + bb.y, 0.f);
                v.z = fmaxf(v.z + bb.z, 0.f); v.w = fmaxf(v.w + bb.w, 0.f);
            }
            *reinterpret_cast<float4*>(&sA[r * 68 + q * 4]) = v;
        }
        __syncthreads();

#pragma unroll
        for (int ksl = 0; ksl < 8; ksl++) {
            const int ks = chunk * 8 + ksl;
            const int c  = ksl * 8 + t;
            const int r0 = w * 16 + g;
            // A fragment (one stripe; conflict-free: stride 68 mod 32 = 4)
            float a0 = sA[(r0    ) * 68 + c];
            float a1 = sA[(r0 + 8) * 68 + c];
            float a2 = sA[(r0    ) * 68 + c + 4];
            float a3 = sA[(r0 + 8) * 68 + c + 4];
            float h0 = tf32_hi(a0), h1 = tf32_hi(a1),
                  h2 = tf32_hi(a2), h3 = tf32_hi(a3);
            float l0 = a0 - h0, l1 = a1 - h1, l2 = a2 - h2, l3 = a3 - h3;

            const float4* bp = &Bfrag[(ks * 16 + blockIdx.y * 8) * 32 + lane];
#pragma unroll
            for (int nt8 = 0; nt8 < 8; nt8++) {
                float4 b = bp[nt8 * 32];
                mma_tf32(acc[nt8], h0, h1, h2, h3, b.x, b.y);  // hi*hi
                mma_tf32(acc[nt8], h0, h1, h2, h3, b.z, b.w);  // hi*lo
                mma_tf32(acc[nt8], l0, l1, l2, l3, b.x, b.y);  // lo*hi
            }
        }
        __syncthreads();
    }

    // epilogue: d0,d1 -> (row g, cols 2t,2t+1); d2,d3 -> row g+8
    int r0 = block_row + w * 16 + g;
#pragma unroll
    for (int nt8 = 0; nt8 < 8; nt8++) {
        int col = col_base + nt8 * 8 + t * 2;
        if (r0 < NN)
            *reinterpret_cast<float2*>(&Out[r0 * FD + col]) =
                make_float2(acc[nt8].x, acc[nt8].y);
        if (r0 + 8 < NN)
            *reinterpret_cast<float2*>(&Out[(r0 + 8) * FD + col]) =
                make_float2(acc[nt8].z, acc[nt8].w);
    }
}

// ---------------------------------------------------------------------------
// CSR gather aggregation: warp per dst node, lane = one float4 of features.
__global__ void k_gather() {
    int gid = blockIdx.x * blockDim.x + threadIdx.x;
    int n = gid >> 5;
    int lane = gid & 31;
    if (n >= NN) return;

    const float4* hw4 = reinterpret_cast<const float4*>(g_hw);
    int start = g_rowstart[n];
    int cnt   = g_deg[n];

    float4 acc = make_float4(0.f, 0.f, 0.f, 0.f);
    int j = 0;
    for (; j + 4 <= cnt; j += 4) {
        int s0 = g_csrc[start + j + 0];
        int s1 = g_csrc[start + j + 1];
        int s2 = g_csrc[start + j + 2];
        int s3 = g_csrc[start + j + 3];
        float w0 = g_dis[s0], w1 = g_dis[s1], w2 = g_dis[s2], w3 = g_dis[s3];
        float4 v0 = hw4[s0 * 32 + lane];
        float4 v1 = hw4[s1 * 32 + lane];
        float4 v2 = hw4[s2 * 32 + lane];
        float4 v3 = hw4[s3 * 32 + lane];
        acc.x += w0 * v0.x + w1 * v1.x + w2 * v2.x + w3 * v3.x;
        acc.y += w0 * v0.y + w1 * v1.y + w2 * v2.y + w3 * v3.y;
        acc.z += w0 * v0.z + w1 * v1.z + w2 * v2.z + w3 * v3.z;
        acc.w += w0 * v0.w + w1 * v1.w + w2 * v2.w + w3 * v3.w;
    }
    for (; j < cnt; j++) {
        int s = g_csrc[start + j];
        float w = g_dis[s];
        float4 v = hw4[s * 32 + lane];
        acc.x += w * v.x; acc.y += w * v.y;
        acc.z += w * v.z; acc.w += w * v.w;
    }
    float dd = g_dis[n];
    float w2s = dd * dd;
    float4 self = hw4[n * 32 + lane];
    float4 o = make_float4(dd * acc.x + w2s * self.x,
                           dd * acc.y + w2s * self.y,
                           dd * acc.z + w2s * self.z,
                           dd * acc.w + w2s * self.w);
    reinterpret_cast<float4*>(g_agg)[n * 32 + lane] = o;
}

// ---------------------------------------------------------------------------
// pooling over contiguous graph segments + readout, fused. Block per graph.
__global__ void __launch_bounds__(128) k_pool_final(
    const float* __restrict__ b2, const float* __restrict__ Wlin,
    const float* __restrict__ blin, float* __restrict__ out)
{
    __shared__ float sh[128];
    int g = blockIdx.x;
    int f = threadIdx.x;
    int n0 = g_gstart[g], n1 = g_gstart[g + 1];
    int cnt = n1 - n0;

    float acc = 0.0f;
#pragma unroll 4
    for (int n = n0; n < n1; n++) acc += g_agg[n * FD + f];

    float inv = (cnt > 0) ? 1.0f / (float)cnt : 0.0f;
    float pooled = acc * inv + ((cnt > 0) ? b2[f] : 0.0f);
    sh[f] = pooled * Wlin[f];
    __syncthreads();
#pragma unroll
    for (int off = 64; off > 0; off >>= 1) {
        if (f < off) sh[f] += sh[f + off];
        __syncthreads();
    }
    if (f == 0) out[g] = sh[0] + blin[0];
}

// ---------------------------------------------------------------------------
extern "C" void kernel_launch(void* const* d_in, const int* in_sizes, int n_in,
                              void* d_out, int out_size)
{
    const float* x     = (const float*)d_in[0];
    const int*   ei    = (const int*)d_in[1];     // int32
    const int*   batch = (const int*)d_in[2];     // int32
    const float* W1    = (const float*)d_in[3];
    const float* b1    = (const float*)d_in[4];
    const float* W2    = (const float*)d_in[5];
    const float* b2    = (const float*)d_in[6];
    const float* Wlin  = (const float*)d_in[7];
    const float* blin  = (const float*)d_in[8];
    float* out = (float*)d_out;

    void *p_hw, *p_agg, *p_bf1, *p_bf2;
    cudaGetSymbolAddress(&p_hw,  g_hw);
    cudaGetSymbolAddress(&p_agg, g_agg);
    cudaGetSymbolAddress(&p_bf1, g_bfrag1);
    cudaGetSymbolAddress(&p_bf2, g_bfrag2);
    float*  hw  = (float*)p_hw;
    float*  agg = (float*)p_agg;
    float4* bf1 = (float4*)p_bf1;
    float4* bf2 = (float4*)p_bf2;

    const int T = 256;
    const int nn_blocks = (NN + T - 1) / T;
    const int ne_blocks = (NE + T - 1) / T;
    const dim3 gemm_grid((NN + 127) / 128, 2);
    const int gat_blocks = (NN * 32 + T - 1) / T;

    // Launch order keeps gemm<false> at my launch index 3 (0-based) so the
    // ncu capture window (-s 5 -c 1, 2 harness pre-launches) lands on it.
    k_zero       <<<nn_blocks, T>>>();
    k_count      <<<ne_blocks, T>>>(ei);
    k_bfrag      <<<32, 256>>>(W1, bf1);
    k_gemm<false><<<gemm_grid, T>>>(x, nullptr, hw, bf1);    // layer-1 GEMM
    k_bfrag      <<<32, 256>>>(W2, bf2);
    k_scan1      <<<NB_SCAN, SCAN_B>>>();
    k_scan2      <<<1, 128>>>();
    k_scan3      <<<nn_blocks, T>>>();
    k_fill       <<<ne_blocks, T>>>(ei);
    k_gstart     <<<(NN + 1 + T - 1) / T, T>>>(batch);

    // Layer 1 aggregation, then layer 2
    k_gather     <<<gat_blocks, T>>>();
    k_gemm<true> <<<gemm_grid, T>>>(agg, b1, hw, bf2);
    k_gather     <<<gat_blocks, T>>>();

    // Mean-pool (contiguous segments) + readout, b2 folded with empty-graph guard
    k_pool_final <<<NG, 128>>>(b2, Wlin, blin, out);
}

// round 15
// speedup vs baseline: 1.1180x; 1.1180x over previous
#include <cuda_runtime.h>

#define NN 100000
#define NE 600000
#define NG 512
#define FD 128
#define SCAN_B 1024
#define NB_SCAN ((NN + SCAN_B - 1) / SCAN_B)   // 98

// Scratch (allocation-free rule: __device__ globals). No float atomics anywhere.
__device__ float g_hw [NN * FD];   // h @ W
__device__ float g_agg[NN * FD];   // aggregated layer output
__device__ float g_dis[NN];        // deg^{-1/2}
__device__ int   g_deg[NN];        // in-degree (excluding self loop)
__device__ int   g_scan[NN];       // inclusive per-block scan
__device__ int   g_bsum[NB_SCAN];
__device__ int   g_boff[NB_SCAN];
__device__ int   g_rowstart[NN];   // CSR row starts (exclusive scan)
__device__ int   g_cursor[NN];     // fill cursors
__device__ int   g_csrc[NE];       // CSR: src lists grouped by dst
__device__ int   g_gstart[NG + 1]; // graph segment starts (batch is sorted)
__device__ float4 g_bfrag1[16 * 16 * 32];  // W1 mma fragments {b0h,b1h,b0l,b1l}
__device__ float4 g_bfrag2[16 * 16 * 32];  // W2 mma fragments

// ---------------------------------------------------------------------------
__global__ void k_zero() {
    int i = blockIdx.x * blockDim.x + threadIdx.x;
    if (i < NN) g_deg[i] = 0;
}

__global__ void k_count(const int* __restrict__ ei) {
    int e = blockIdx.x * blockDim.x + threadIdx.x;
    if (e < NE) atomicAdd(&g_deg[ei[NE + e]], 1);
}

__global__ void __launch_bounds__(SCAN_B) k_scan1() {
    __shared__ int s[SCAN_B];
    int tid = threadIdx.x;
    int i = blockIdx.x * SCAN_B + tid;
    s[tid] = (i < NN) ? g_deg[i] : 0;
    __syncthreads();
#pragma unroll
    for (int off = 1; off < SCAN_B; off <<= 1) {
        int v = (tid >= off) ? s[tid - off] : 0;
        __syncthreads();
        s[tid] += v;
        __syncthreads();
    }
    if (i < NN) g_scan[i] = s[tid];
    if (tid == SCAN_B - 1) g_bsum[blockIdx.x] = s[tid];
}

__global__ void __launch_bounds__(128) k_scan2() {
    __shared__ int s[128];
    int t = threadIdx.x;
    int v = (t < NB_SCAN) ? g_bsum[t] : 0;
    s[t] = v;
    __syncthreads();
#pragma unroll
    for (int off = 1; off < 128; off <<= 1) {
        int u = (t >= off) ? s[t - off] : 0;
        __syncthreads();
        s[t] += u;
        __syncthreads();
    }
    if (t < NB_SCAN) g_boff[t] = s[t] - v;   // exclusive
}

__global__ void k_scan3() {
    int i = blockIdx.x * blockDim.x + threadIdx.x;
    if (i < NN) {
        int excl = g_scan[i] + g_boff[i >> 10] - g_deg[i];
        g_rowstart[i] = excl;
        g_cursor[i]   = excl;
        g_dis[i] = rsqrtf(1.0f + (float)g_deg[i]);
    }
}

__global__ void k_fill(const int* __restrict__ ei) {
    int e = blockIdx.x * blockDim.x + threadIdx.x;
    if (e < NE) {
        int s = ei[e];
        int d = ei[NE + e];
        int pos = atomicAdd(&g_cursor[d], 1);
        g_csrc[pos] = s;
    }
}

__global__ void k_gstart(const int* __restrict__ batch) {
    int i = blockIdx.x * blockDim.x + threadIdx.x;
    if (i <= NN) {
        int prev = (i == 0) ? -1 : batch[i - 1];
        int cur  = (i < NN) ? batch[i] : NG;
        for (int g = prev + 1; g <= cur; g++) g_gstart[g] = i;
    }
}

// ---------------------------------------------------------------------------
__device__ __forceinline__ float tf32_hi(float a) {
    return __uint_as_float(__float_as_uint(a) & 0xffffe000u);
}

// Precompute W mma fragments (one-time, shared by all GEMM blocks).
// Layout: [ks(16)][nt(16)][lane(32)] float4 = {b0hi, b1hi, b0lo, b1lo}
// lane(g,t): b0 = W[ks*8+t][nt*8+g], b1 = W[ks*8+t+4][nt*8+g]
__global__ void k_bfrag(const float* __restrict__ W, float4* __restrict__ out) {
    int i = blockIdx.x * blockDim.x + threadIdx.x;
    if (i >= 16 * 16 * 32) return;
    int lane = i & 31, nt = (i >> 5) & 15, ks = i >> 9;
    int g = lane >> 2, t = lane & 3;
    int n = nt * 8 + g;
    float b0 = W[(ks * 8 + t) * FD + n];
    float b1 = W[(ks * 8 + t + 4) * FD + n];
    float b0h = tf32_hi(b0), b1h = tf32_hi(b1);
    out[i] = make_float4(b0h, b1h, b0 - b0h, b1 - b1h);
}

__device__ __forceinline__ void mma_tf32(float4& d, float a0, float a1, float a2,
                                         float a3, float b0, float b1) {
    asm volatile(
        "mma.sync.aligned.m16n8k8.row.col.f32.tf32.tf32.f32 "
        "{%0,%1,%2,%3}, {%4,%5,%6,%7}, {%8,%9}, {%0,%1,%2,%3};\n"
        : "+f"(d.x), "+f"(d.y), "+f"(d.z), "+f"(d.w)
        : "r"(__float_as_uint(a0)), "r"(__float_as_uint(a1)),
          "r"(__float_as_uint(a2)), "r"(__float_as_uint(a3)),
          "r"(__float_as_uint(b0)), "r"(__float_as_uint(b1)));
}

// Zero-filling 16B async copy (src_size=0 -> fill with zeros).
__device__ __forceinline__ void cp_async16_z(float* smem, const float* gmem, int src_sz) {
    unsigned s = (unsigned)__cvta_generic_to_shared(smem);
    asm volatile("cp.async.cg.shared.global [%0], [%1], 16, %2;"
                 :: "r"(s), "l"(gmem), "r"(src_sz) : "memory");
}

// Tensor-core GEMM: Out[NN,128] = f(A)[NN,128] @ W[128,128], split-TF32.
// Block 128x128 (R13 tile), 256 threads, 2 blocks/SM.
// cp.async DOUBLE-BUFFERED A staging: BK=32, 4 chunks, prefetch c+2 during c.
// bias+relu applied at fragment-load (bias staged in smem) so cp.async stays raw.
// Buffer row stride 36 (mod 32 = 4): conflict-free fragment LDS.
template <bool RELU_BIAS>
__global__ void __launch_bounds__(256, 2) k_gemm(
    const float* __restrict__ A, const float* __restrict__ bias,
    float* __restrict__ Out, const float4* __restrict__ Bfrag)
{
    __shared__ float sA[2][128 * 36];   // double-buffered A chunk (128 rows x 32 k)
    __shared__ float sBias[FD];

    const int block_row = blockIdx.x * 128;
    const int tid  = threadIdx.x;
    const int lane = tid & 31;
    const int w    = tid >> 5;
    const int rw   = w >> 1;        // warp row group (32 rows)
    const int cw   = w & 1;         // warp col half (64 cols)
    const int g    = lane >> 2, t = lane & 3;

    if (RELU_BIAS && tid < 32)
        *reinterpret_cast<float4*>(&sBias[tid * 4]) =
            *reinterpret_cast<const float4*>(&bias[tid * 4]);

    float4 acc0[8], acc1[8];
#pragma unroll
    for (int i = 0; i < 8; i++) {
        acc0[i] = make_float4(0.f, 0.f, 0.f, 0.f);
        acc1[i] = make_float4(0.f, 0.f, 0.f, 0.f);
    }

    // stage one 128x32 chunk into buffer (chunk&1) via cp.async
    auto stage = [&](int chunk) {
        const int k0c = chunk * 32;
        float* buf = sA[chunk & 1];
#pragma unroll
        for (int ii = 0; ii < 4; ii++) {
            int idx = tid + ii * 256;           // 1024 float4 total
            int r = idx >> 3, q = idx & 7;
            int row = block_row + r;
            const float* src = &A[(size_t)row * FD + k0c + q * 4];
            cp_async16_z(&buf[r * 36 + q * 4], src, row < NN ? 16 : 0);
        }
        asm volatile("cp.async.commit_group;" ::: "memory");
    };

    stage(0);
    stage(1);

#pragma unroll
    for (int chunk = 0; chunk < 4; chunk++) {
        if (chunk == 3) asm volatile("cp.async.wait_group 0;" ::: "memory");
        else            asm volatile("cp.async.wait_group 1;" ::: "memory");
        __syncthreads();

        const float* buf = sA[chunk & 1];
#pragma unroll
        for (int ksl = 0; ksl < 4; ksl++) {
            const int ks = chunk * 4 + ksl;
            const int c  = ksl * 8 + t;
            const int r0 = rw * 32 + g;
            // A fragments, both stripes (conflict-free: stride 36 mod 32 = 4)
            float a00 = buf[(r0     ) * 36 + c];
            float a01 = buf[(r0 +  8) * 36 + c];
            float a02 = buf[(r0     ) * 36 + c + 4];
            float a03 = buf[(r0 +  8) * 36 + c + 4];
            float a10 = buf[(r0 + 16) * 36 + c];
            float a11 = buf[(r0 + 24) * 36 + c];
            float a12 = buf[(r0 + 16) * 36 + c + 4];
            float a13 = buf[(r0 + 24) * 36 + c + 4];
            if (RELU_BIAS) {
                float b0v = sBias[chunk * 32 + c];
                float b1v = sBias[chunk * 32 + c + 4];
                a00 = fmaxf(a00 + b0v, 0.f); a01 = fmaxf(a01 + b0v, 0.f);
                a02 = fmaxf(a02 + b1v, 0.f); a03 = fmaxf(a03 + b1v, 0.f);
                a10 = fmaxf(a10 + b0v, 0.f); a11 = fmaxf(a11 + b0v, 0.f);
                a12 = fmaxf(a12 + b1v, 0.f); a13 = fmaxf(a13 + b1v, 0.f);
            }
            // register hi/lo split
            float h00 = tf32_hi(a00), h01 = tf32_hi(a01),
                  h02 = tf32_hi(a02), h03 = tf32_hi(a03);
            float h10 = tf32_hi(a10), h11 = tf32_hi(a11),
                  h12 = tf32_hi(a12), h13 = tf32_hi(a13);
            float l00 = a00 - h00, l01 = a01 - h01, l02 = a02 - h02, l03 = a03 - h03;
            float l10 = a10 - h10, l11 = a11 - h11, l12 = a12 - h12, l13 = a13 - h13;

            const float4* bp = &Bfrag[(ks * 16 + cw * 8) * 32 + lane];
#pragma unroll
            for (int nt8 = 0; nt8 < 8; nt8++) {
                float4 b = bp[nt8 * 32];
                // stripe 0: hi*hi, hi*lo, lo*hi
                mma_tf32(acc0[nt8], h00, h01, h02, h03, b.x, b.y);
                mma_tf32(acc0[nt8], h00, h01, h02, h03, b.z, b.w);
                mma_tf32(acc0[nt8], l00, l01, l02, l03, b.x, b.y);
                // stripe 1
                mma_tf32(acc1[nt8], h10, h11, h12, h13, b.x, b.y);
                mma_tf32(acc1[nt8], h10, h11, h12, h13, b.z, b.w);
                mma_tf32(acc1[nt8], l10, l11, l12, l13, b.x, b.y);
            }
        }
        __syncthreads();
        if (chunk + 2 < 4) stage(chunk + 2);
    }

    // epilogue: d0,d1 -> (row g, cols 2t,2t+1); d2,d3 -> row g+8
#pragma unroll
    for (int s = 0; s < 2; s++) {
        const float4* accs = s ? acc1 : acc0;
        int r0 = block_row + rw * 32 + s * 16 + g;
#pragma unroll
        for (int nt8 = 0; nt8 < 8; nt8++) {
            int col = cw * 64 + nt8 * 8 + t * 2;
            if (r0 < NN)
                *reinterpret_cast<float2*>(&Out[r0 * FD + col]) =
                    make_float2(accs[nt8].x, accs[nt8].y);
            if (r0 + 8 < NN)
                *reinterpret_cast<float2*>(&Out[(r0 + 8) * FD + col]) =
                    make_float2(accs[nt8].z, accs[nt8].w);
        }
    }
}

// ---------------------------------------------------------------------------
// CSR gather aggregation: warp per dst node, lane = one float4 of features.
__global__ void k_gather() {
    int gid = blockIdx.x * blockDim.x + threadIdx.x;
    int n = gid >> 5;
    int lane = gid & 31;
    if (n >= NN) return;

    const float4* hw4 = reinterpret_cast<const float4*>(g_hw);
    int start = g_rowstart[n];
    int cnt   = g_deg[n];

    float4 acc = make_float4(0.f, 0.f, 0.f, 0.f);
    int j = 0;
    for (; j + 4 <= cnt; j += 4) {
        int s0 = g_csrc[start + j + 0];
        int s1 = g_csrc[start + j + 1];
        int s2 = g_csrc[start + j + 2];
        int s3 = g_csrc[start + j + 3];
        float w0 = g_dis[s0], w1 = g_dis[s1], w2 = g_dis[s2], w3 = g_dis[s3];
        float4 v0 = hw4[s0 * 32 + lane];
        float4 v1 = hw4[s1 * 32 + lane];
        float4 v2 = hw4[s2 * 32 + lane];
        float4 v3 = hw4[s3 * 32 + lane];
        acc.x += w0 * v0.x + w1 * v1.x + w2 * v2.x + w3 * v3.x;
        acc.y += w0 * v0.y + w1 * v1.y + w2 * v2.y + w3 * v3.y;
        acc.z += w0 * v0.z + w1 * v1.z + w2 * v2.z + w3 * v3.z;
        acc.w += w0 * v0.w + w1 * v1.w + w2 * v2.w + w3 * v3.w;
    }
    for (; j < cnt; j++) {
        int s = g_csrc[start + j];
        float w = g_dis[s];
        float4 v = hw4[s * 32 + lane];
        acc.x += w * v.x; acc.y += w * v.y;
        acc.z += w * v.z; acc.w += w * v.w;
    }
    float dd = g_dis[n];
    float w2s = dd * dd;
    float4 self = hw4[n * 32 + lane];
    float4 o = make_float4(dd * acc.x + w2s * self.x,
                           dd * acc.y + w2s * self.y,
                           dd * acc.z + w2s * self.z,
                           dd * acc.w + w2s * self.w);
    reinterpret_cast<float4*>(g_agg)[n * 32 + lane] = o;
}

// ---------------------------------------------------------------------------
// pooling over contiguous graph segments + readout, fused. Block per graph.
__global__ void __launch_bounds__(128) k_pool_final(
    const float* __restrict__ b2, const float* __restrict__ Wlin,
    const float* __restrict__ blin, float* __restrict__ out)
{
    __shared__ float sh[128];
    int g = blockIdx.x;
    int f = threadIdx.x;
    int n0 = g_gstart[g], n1 = g_gstart[g + 1];
    int cnt = n1 - n0;

    float acc = 0.0f;
#pragma unroll 4
    for (int n = n0; n < n1; n++) acc += g_agg[n * FD + f];

    float inv = (cnt > 0) ? 1.0f / (float)cnt : 0.0f;
    float pooled = acc * inv + ((cnt > 0) ? b2[f] : 0.0f);
    sh[f] = pooled * Wlin[f];
    __syncthreads();
#pragma unroll
    for (int off = 64; off > 0; off >>= 1) {
        if (f < off) sh[f] += sh[f + off];
        __syncthreads();
    }
    if (f == 0) out[g] = sh[0] + blin[0];
}

// ---------------------------------------------------------------------------
extern "C" void kernel_launch(void* const* d_in, const int* in_sizes, int n_in,
                              void* d_out, int out_size)
{
    const float* x     = (const float*)d_in[0];
    const int*   ei    = (const int*)d_in[1];     // int32
    const int*   batch = (const int*)d_in[2];     // int32
    const float* W1    = (const float*)d_in[3];
    const float* b1    = (const float*)d_in[4];
    const float* W2    = (const float*)d_in[5];
    const float* b2    = (const float*)d_in[6];
    const float* Wlin  = (const float*)d_in[7];
    const float* blin  = (const float*)d_in[8];
    float* out = (float*)d_out;

    void *p_hw, *p_agg, *p_bf1, *p_bf2;
    cudaGetSymbolAddress(&p_hw,  g_hw);
    cudaGetSymbolAddress(&p_agg, g_agg);
    cudaGetSymbolAddress(&p_bf1, g_bfrag1);
    cudaGetSymbolAddress(&p_bf2, g_bfrag2);
    float*  hw  = (float*)p_hw;
    float*  agg = (float*)p_agg;
    float4* bf1 = (float4*)p_bf1;
    float4* bf2 = (float4*)p_bf2;

    const int T = 256;
    const int nn_blocks = (NN + T - 1) / T;
    const int ne_blocks = (NE + T - 1) / T;
    const int gemm_blocks = (NN + 127) / 128;
    const int gat_blocks = (NN * 32 + T - 1) / T;

    // Launch order keeps gemm<false> at my launch index 3 (0-based) so the
    // ncu capture window (-s 5 -c 1, 2 harness pre-launches) lands on it.
    k_zero       <<<nn_blocks, T>>>();
    k_count      <<<ne_blocks, T>>>(ei);
    k_bfrag      <<<32, 256>>>(W1, bf1);
    k_gemm<false><<<gemm_blocks, T>>>(x, nullptr, hw, bf1);  // layer-1 GEMM
    k_bfrag      <<<32, 256>>>(W2, bf2);
    k_scan1      <<<NB_SCAN, SCAN_B>>>();
    k_scan2      <<<1, 128>>>();
    k_scan3      <<<nn_blocks, T>>>();
    k_fill       <<<ne_blocks, T>>>(ei);
    k_gstart     <<<(NN + 1 + T - 1) / T, T>>>(batch);

    // Layer 1 aggregation, then layer 2
    k_gather     <<<gat_blocks, T>>>();
    k_gemm<true> <<<gemm_blocks, T>>>(agg, b1, hw, bf2);
    k_gather     <<<gat_blocks, T>>>();

    // Mean-pool (contiguous segments) + readout, b2 folded with empty-graph guard
    k_pool_final <<<NG, 128>>>(b2, Wlin, blin, out);
}

// round 16
// speedup vs baseline: 1.1803x; 1.0557x over previous
#include <cuda_runtime.h>

#define NN 100000
#define NE 600000
#define NG 512
#define FD 128
#define SCAN_B 1024
#define NB_SCAN ((NN + SCAN_B - 1) / SCAN_B)   // 98

// Scratch (allocation-free rule: __device__ globals). No float atomics anywhere.
__device__ float g_hw [NN * FD];   // h @ W
__device__ float g_agg[NN * FD];   // aggregated layer output
__device__ float g_dis[NN];        // deg^{-1/2}
__device__ int   g_deg[NN];        // in-degree (excluding self loop)
__device__ int   g_scan[NN];       // inclusive per-block scan
__device__ int   g_bsum[NB_SCAN];
__device__ int   g_boff[NB_SCAN];
__device__ int   g_rowstart[NN];   // CSR row starts (exclusive scan)
__device__ int   g_cursor[NN];     // fill cursors
__device__ int   g_csrc[NE];       // CSR: src lists grouped by dst
__device__ int   g_gstart[NG + 1]; // graph segment starts (batch is sorted)
__device__ float4 g_bfrag1[16 * 16 * 32];  // W1 mma fragments {b0h,b1h,b0l,b1l}
__device__ float4 g_bfrag2[16 * 16 * 32];  // W2 mma fragments

// ---------------------------------------------------------------------------
__global__ void k_zero() {
    int i = blockIdx.x * blockDim.x + threadIdx.x;
    if (i < NN) g_deg[i] = 0;
}

__global__ void k_count(const int* __restrict__ ei) {
    int e = blockIdx.x * blockDim.x + threadIdx.x;
    if (e < NE) atomicAdd(&g_deg[ei[NE + e]], 1);
}

__global__ void __launch_bounds__(SCAN_B) k_scan1() {
    __shared__ int s[SCAN_B];
    int tid = threadIdx.x;
    int i = blockIdx.x * SCAN_B + tid;
    s[tid] = (i < NN) ? g_deg[i] : 0;
    __syncthreads();
#pragma unroll
    for (int off = 1; off < SCAN_B; off <<= 1) {
        int v = (tid >= off) ? s[tid - off] : 0;
        __syncthreads();
        s[tid] += v;
        __syncthreads();
    }
    if (i < NN) g_scan[i] = s[tid];
    if (tid == SCAN_B - 1) g_bsum[blockIdx.x] = s[tid];
}

__global__ void __launch_bounds__(128) k_scan2() {
    __shared__ int s[128];
    int t = threadIdx.x;
    int v = (t < NB_SCAN) ? g_bsum[t] : 0;
    s[t] = v;
    __syncthreads();
#pragma unroll
    for (int off = 1; off < 128; off <<= 1) {
        int u = (t >= off) ? s[t - off] : 0;
        __syncthreads();
        s[t] += u;
        __syncthreads();
    }
    if (t < NB_SCAN) g_boff[t] = s[t] - v;   // exclusive
}

__global__ void k_scan3() {
    int i = blockIdx.x * blockDim.x + threadIdx.x;
    if (i < NN) {
        int excl = g_scan[i] + g_boff[i >> 10] - g_deg[i];
        g_rowstart[i] = excl;
        g_cursor[i]   = excl;
        g_dis[i] = rsqrtf(1.0f + (float)g_deg[i]);
    }
}

__global__ void k_fill(const int* __restrict__ ei) {
    int e = blockIdx.x * blockDim.x + threadIdx.x;
    if (e < NE) {
        int s = ei[e];
        int d = ei[NE + e];
        int pos = atomicAdd(&g_cursor[d], 1);
        g_csrc[pos] = s;
    }
}

__global__ void k_gstart(const int* __restrict__ batch) {
    int i = blockIdx.x * blockDim.x + threadIdx.x;
    if (i <= NN) {
        int prev = (i == 0) ? -1 : batch[i - 1];
        int cur  = (i < NN) ? batch[i] : NG;
        for (int g = prev + 1; g <= cur; g++) g_gstart[g] = i;
    }
}

// ---------------------------------------------------------------------------
__device__ __forceinline__ float tf32_hi(float a) {
    return __uint_as_float(__float_as_uint(a) & 0xffffe000u);
}

// Precompute W mma fragments (one-time, shared by all GEMM blocks).
// Layout: [ks(16)][nt(16)][lane(32)] float4 = {b0hi, b1hi, b0lo, b1lo}
// lane(g,t): b0 = W[ks*8+t][nt*8+g], b1 = W[ks*8+t+4][nt*8+g]
__global__ void k_bfrag(const float* __restrict__ W, float4* __restrict__ out) {
    int i = blockIdx.x * blockDim.x + threadIdx.x;
    if (i >= 16 * 16 * 32) return;
    int lane = i & 31, nt = (i >> 5) & 15, ks = i >> 9;
    int g = lane >> 2, t = lane & 3;
    int n = nt * 8 + g;
    float b0 = W[(ks * 8 + t) * FD + n];
    float b1 = W[(ks * 8 + t + 4) * FD + n];
    float b0h = tf32_hi(b0), b1h = tf32_hi(b1);
    out[i] = make_float4(b0h, b1h, b0 - b0h, b1 - b1h);
}

__device__ __forceinline__ void mma_tf32(float4& d, float a0, float a1, float a2,
                                         float a3, float b0, float b1) {
    asm volatile(
        "mma.sync.aligned.m16n8k8.row.col.f32.tf32.tf32.f32 "
        "{%0,%1,%2,%3}, {%4,%5,%6,%7}, {%8,%9}, {%0,%1,%2,%3};\n"
        : "+f"(d.x), "+f"(d.y), "+f"(d.z), "+f"(d.w)
        : "r"(__float_as_uint(a0)), "r"(__float_as_uint(a1)),
          "r"(__float_as_uint(a2)), "r"(__float_as_uint(a3)),
          "r"(__float_as_uint(b0)), "r"(__float_as_uint(b1)));
}

// Zero-filling 16B async copy (src_size=0 -> fill with zeros).
__device__ __forceinline__ void cp_async16_z(float* smem, const float* gmem, int src_sz) {
    unsigned s = (unsigned)__cvta_generic_to_shared(smem);
    asm volatile("cp.async.cg.shared.global [%0], [%1], 16, %2;"
                 :: "r"(s), "l"(gmem), "r"(src_sz) : "memory");
}

// Tensor-core GEMM: Out[NN,128] = f(A)[NN,128] @ W[128,128], split-TF32.
// Block 128x128, 256 threads, 2 blocks/SM.
// cp.async DOUBLE-BUFFERED A staging: BK=32, 4 chunks, prefetch c+2 during c.
// bias+relu applied at fragment-load (bias staged in smem) so cp.async stays raw.
// Buffer row stride 36 (mod 32 = 4): conflict-free fragment LDS.
template <bool RELU_BIAS>
__global__ void __launch_bounds__(256, 2) k_gemm(
    const float* __restrict__ A, const float* __restrict__ bias,
    float* __restrict__ Out, const float4* __restrict__ Bfrag)
{
    __shared__ float sA[2][128 * 36];   // double-buffered A chunk (128 rows x 32 k)
    __shared__ float sBias[FD];

    const int block_row = blockIdx.x * 128;
    const int tid  = threadIdx.x;
    const int lane = tid & 31;
    const int w    = tid >> 5;
    const int rw   = w >> 1;        // warp row group (32 rows)
    const int cw   = w & 1;         // warp col half (64 cols)
    const int g    = lane >> 2, t = lane & 3;

    if (RELU_BIAS && tid < 32)
        *reinterpret_cast<float4*>(&sBias[tid * 4]) =
            *reinterpret_cast<const float4*>(&bias[tid * 4]);

    float4 acc0[8], acc1[8];
#pragma unroll
    for (int i = 0; i < 8; i++) {
        acc0[i] = make_float4(0.f, 0.f, 0.f, 0.f);
        acc1[i] = make_float4(0.f, 0.f, 0.f, 0.f);
    }

    // stage one 128x32 chunk into buffer (chunk&1) via cp.async
    auto stage = [&](int chunk) {
        const int k0c = chunk * 32;
        float* buf = sA[chunk & 1];
#pragma unroll
        for (int ii = 0; ii < 4; ii++) {
            int idx = tid + ii * 256;           // 1024 float4 total
            int r = idx >> 3, q = idx & 7;
            int row = block_row + r;
            const float* src = &A[(size_t)row * FD + k0c + q * 4];
            cp_async16_z(&buf[r * 36 + q * 4], src, row < NN ? 16 : 0);
        }
        asm volatile("cp.async.commit_group;" ::: "memory");
    };

    stage(0);
    stage(1);

#pragma unroll
    for (int chunk = 0; chunk < 4; chunk++) {
        if (chunk == 3) asm volatile("cp.async.wait_group 0;" ::: "memory");
        else            asm volatile("cp.async.wait_group 1;" ::: "memory");
        __syncthreads();

        const float* buf = sA[chunk & 1];
#pragma unroll
        for (int ksl = 0; ksl < 4; ksl++) {
            const int ks = chunk * 4 + ksl;
            const int c  = ksl * 8 + t;
            const int r0 = rw * 32 + g;
            // A fragments, both stripes (conflict-free: stride 36 mod 32 = 4)
            float a00 = buf[(r0     ) * 36 + c];
            float a01 = buf[(r0 +  8) * 36 + c];
            float a02 = buf[(r0     ) * 36 + c + 4];
            float a03 = buf[(r0 +  8) * 36 + c + 4];
            float a10 = buf[(r0 + 16) * 36 + c];
            float a11 = buf[(r0 + 24) * 36 + c];
            float a12 = buf[(r0 + 16) * 36 + c + 4];
            float a13 = buf[(r0 + 24) * 36 + c + 4];
            if (RELU_BIAS) {
                float b0v = sBias[chunk * 32 + c];
                float b1v = sBias[chunk * 32 + c + 4];
                a00 = fmaxf(a00 + b0v, 0.f); a01 = fmaxf(a01 + b0v, 0.f);
                a02 = fmaxf(a02 + b1v, 0.f); a03 = fmaxf(a03 + b1v, 0.f);
                a10 = fmaxf(a10 + b0v, 0.f); a11 = fmaxf(a11 + b0v, 0.f);
                a12 = fmaxf(a12 + b1v, 0.f); a13 = fmaxf(a13 + b1v, 0.f);
            }
            // register hi/lo split
            float h00 = tf32_hi(a00), h01 = tf32_hi(a01),
                  h02 = tf32_hi(a02), h03 = tf32_hi(a03);
            float h10 = tf32_hi(a10), h11 = tf32_hi(a11),
                  h12 = tf32_hi(a12), h13 = tf32_hi(a13);
            float l00 = a00 - h00, l01 = a01 - h01, l02 = a02 - h02, l03 = a03 - h03;
            float l10 = a10 - h10, l11 = a11 - h11, l12 = a12 - h12, l13 = a13 - h13;

            const float4* bp = &Bfrag[(ks * 16 + cw * 8) * 32 + lane];
#pragma unroll
            for (int nt8 = 0; nt8 < 8; nt8++) {
                float4 b = bp[nt8 * 32];
                // stripe 0: hi*hi, hi*lo, lo*hi
                mma_tf32(acc0[nt8], h00, h01, h02, h03, b.x, b.y);
                mma_tf32(acc0[nt8], h00, h01, h02, h03, b.z, b.w);
                mma_tf32(acc0[nt8], l00, l01, l02, l03, b.x, b.y);
                // stripe 1
                mma_tf32(acc1[nt8], h10, h11, h12, h13, b.x, b.y);
                mma_tf32(acc1[nt8], h10, h11, h12, h13, b.z, b.w);
                mma_tf32(acc1[nt8], l10, l11, l12, l13, b.x, b.y);
            }
        }
        __syncthreads();
        if (chunk + 2 < 4) stage(chunk + 2);
    }

    // epilogue: d0,d1 -> (row g, cols 2t,2t+1); d2,d3 -> row g+8
#pragma unroll
    for (int s = 0; s < 2; s++) {
        const float4* accs = s ? acc1 : acc0;
        int r0 = block_row + rw * 32 + s * 16 + g;
#pragma unroll
        for (int nt8 = 0; nt8 < 8; nt8++) {
            int col = cw * 64 + nt8 * 8 + t * 2;
            if (r0 < NN)
                *reinterpret_cast<float2*>(&Out[r0 * FD + col]) =
                    make_float2(accs[nt8].x, accs[nt8].y);
            if (r0 + 8 < NN)
                *reinterpret_cast<float2*>(&Out[(r0 + 8) * FD + col]) =
                    make_float2(accs[nt8].z, accs[nt8].w);
        }
    }
}

// ---------------------------------------------------------------------------
// CSR gather aggregation: warp per dst node, lane = one float4 of features.
__global__ void k_gather() {
    int gid = blockIdx.x * blockDim.x + threadIdx.x;
    int n = gid >> 5;
    int lane = gid & 31;
    if (n >= NN) return;

    const float4* hw4 = reinterpret_cast<const float4*>(g_hw);
    int start = g_rowstart[n];
    int cnt   = g_deg[n];

    float4 acc = make_float4(0.f, 0.f, 0.f, 0.f);
    int j = 0;
    for (; j + 4 <= cnt; j += 4) {
        int s0 = g_csrc[start + j + 0];
        int s1 = g_csrc[start + j + 1];
        int s2 = g_csrc[start + j + 2];
        int s3 = g_csrc[start + j + 3];
        float w0 = g_dis[s0], w1 = g_dis[s1], w2 = g_dis[s2], w3 = g_dis[s3];
        float4 v0 = hw4[s0 * 32 + lane];
        float4 v1 = hw4[s1 * 32 + lane];
        float4 v2 = hw4[s2 * 32 + lane];
        float4 v3 = hw4[s3 * 32 + lane];
        acc.x += w0 * v0.x + w1 * v1.x + w2 * v2.x + w3 * v3.x;
        acc.y += w0 * v0.y + w1 * v1.y + w2 * v2.y + w3 * v3.y;
        acc.z += w0 * v0.z + w1 * v1.z + w2 * v2.z + w3 * v3.z;
        acc.w += w0 * v0.w + w1 * v1.w + w2 * v2.w + w3 * v3.w;
    }
    for (; j < cnt; j++) {
        int s = g_csrc[start + j];
        float w = g_dis[s];
        float4 v = hw4[s * 32 + lane];
        acc.x += w * v.x; acc.y += w * v.y;
        acc.z += w * v.z; acc.w += w * v.w;
    }
    float dd = g_dis[n];
    float w2s = dd * dd;
    float4 self = hw4[n * 32 + lane];
    float4 o = make_float4(dd * acc.x + w2s * self.x,
                           dd * acc.y + w2s * self.y,
                           dd * acc.z + w2s * self.z,
                           dd * acc.w + w2s * self.w);
    reinterpret_cast<float4*>(g_agg)[n * 32 + lane] = o;
}

// ---------------------------------------------------------------------------
// pooling over contiguous graph segments + readout, fused. Block per graph.
__global__ void __launch_bounds__(128) k_pool_final(
    const float* __restrict__ b2, const float* __restrict__ Wlin,
    const float* __restrict__ blin, float* __restrict__ out)
{
    __shared__ float sh[128];
    int g = blockIdx.x;
    int f = threadIdx.x;
    int n0 = g_gstart[g], n1 = g_gstart[g + 1];
    int cnt = n1 - n0;

    float acc = 0.0f;
#pragma unroll 4
    for (int n = n0; n < n1; n++) acc += g_agg[n * FD + f];

    float inv = (cnt > 0) ? 1.0f / (float)cnt : 0.0f;
    float pooled = acc * inv + ((cnt > 0) ? b2[f] : 0.0f);
    sh[f] = pooled * Wlin[f];
    __syncthreads();
#pragma unroll
    for (int off = 64; off > 0; off >>= 1) {
        if (f < off) sh[f] += sh[f + off];
        __syncthreads();
    }
    if (f == 0) out[g] = sh[0] + blin[0];
}

// ---------------------------------------------------------------------------
extern "C" void kernel_launch(void* const* d_in, const int* in_sizes, int n_in,
                              void* d_out, int out_size)
{
    const float* x     = (const float*)d_in[0];
    const int*   ei    = (const int*)d_in[1];     // int32
    const int*   batch = (const int*)d_in[2];     // int32
    const float* W1    = (const float*)d_in[3];
    const float* b1    = (const float*)d_in[4];
    const float* W2    = (const float*)d_in[5];
    const float* b2    = (const float*)d_in[6];
    const float* Wlin  = (const float*)d_in[7];
    const float* blin  = (const float*)d_in[8];
    float* out = (float*)d_out;

    void *p_hw, *p_agg, *p_bf1, *p_bf2;
    cudaGetSymbolAddress(&p_hw,  g_hw);
    cudaGetSymbolAddress(&p_agg, g_agg);
    cudaGetSymbolAddress(&p_bf1, g_bfrag1);
    cudaGetSymbolAddress(&p_bf2, g_bfrag2);
    float*  hw  = (float*)p_hw;
    float*  agg = (float*)p_agg;
    float4* bf1 = (float4*)p_bf1;
    float4* bf2 = (float4*)p_bf2;

    // Side stream + fork/join events (lazy one-time init; host-side objects,
    // created during the first non-captured correctness call).
    static cudaStream_t s2 = nullptr;
    static cudaEvent_t  eF = nullptr, eJ = nullptr;
    if (!s2) {
        cudaStreamCreateWithFlags(&s2, cudaStreamNonBlocking);
        cudaEventCreateWithFlags(&eF, cudaEventDisableTiming);
        cudaEventCreateWithFlags(&eJ, cudaEventDisableTiming);
    }

    const int T = 256;
    const int nn_blocks = (NN + T - 1) / T;
    const int ne_blocks = (NE + T - 1) / T;
    const int gemm_blocks = (NN + 127) / 128;
    const int gat_blocks = (NN * 32 + T - 1) / T;

    // Fork: CSR build + gstart + bfrag2 run on s2 concurrent with layer-1 GEMM
    // on the main (captured) stream. Join before gather1, which needs both.
    cudaEventRecord(eF, 0);
    cudaStreamWaitEvent(s2, eF, 0);

    k_zero       <<<nn_blocks, T, 0, s2>>>();                 // launch 0
    k_count      <<<ne_blocks, T, 0, s2>>>(ei);               // launch 1
    k_bfrag      <<<32, 256>>>(W1, bf1);                      // launch 2 (main)
    k_gemm<false><<<gemm_blocks, T>>>(x, nullptr, hw, bf1);   // launch 3 (ncu slot)
    k_scan1      <<<NB_SCAN, SCAN_B, 0, s2>>>();
    k_scan2      <<<1, 128, 0, s2>>>();
    k_scan3      <<<nn_blocks, T, 0, s2>>>();
    k_fill       <<<ne_blocks, T, 0, s2>>>(ei);
    k_gstart     <<<(NN + 1 + T - 1) / T, T, 0, s2>>>(batch);
    k_bfrag      <<<32, 256, 0, s2>>>(W2, bf2);

    cudaEventRecord(eJ, s2);
    cudaStreamWaitEvent(0, eJ, 0);

    // Layer 1 aggregation, then layer 2 (main stream)
    k_gather     <<<gat_blocks, T>>>();
    k_gemm<true> <<<gemm_blocks, T>>>(agg, b1, hw, bf2);
    k_gather     <<<gat_blocks, T>>>();

    // Mean-pool (contiguous segments) + readout, b2 folded with empty-graph guard
    k_pool_final <<<NG, 128>>>(b2, Wlin, blin, out);
}

// round 17
// speedup vs baseline: 1.2176x; 1.0316x over previous
#include <cuda_runtime.h>
#include <cuda_fp16.h>

#define NN 100000
#define NE 600000
#define NG 512
#define FD 128
#define SCAN_B 1024
#define NB_SCAN ((NN + SCAN_B - 1) / SCAN_B)   // 98

// Scratch (allocation-free rule: __device__ globals). No float atomics anywhere.
__device__ __half g_hwh[NN * FD];  // h @ W, fp16 (gather payload - halves L2 traffic)
__device__ float g_agg[NN * FD];   // aggregated layer output (fp32)
__device__ float g_dis[NN];        // deg^{-1/2}
__device__ int   g_deg[NN];        // in-degree (excluding self loop)
__device__ int   g_scan[NN];       // inclusive per-block scan
__device__ int   g_bsum[NB_SCAN];
__device__ int   g_boff[NB_SCAN];
__device__ int   g_rowstart[NN];   // CSR row starts (exclusive scan)
__device__ int   g_cursor[NN];     // fill cursors
__device__ int   g_csrc[NE];       // CSR: src lists grouped by dst
__device__ int   g_gstart[NG + 1]; // graph segment starts (batch is sorted)
__device__ float4 g_bfrag1[16 * 16 * 32];  // W1 mma fragments {b0h,b1h,b0l,b1l}
__device__ float4 g_bfrag2[16 * 16 * 32];  // W2 mma fragments

// ---------------------------------------------------------------------------
__global__ void k_zero() {
    int i = blockIdx.x * blockDim.x + threadIdx.x;
    if (i < NN) g_deg[i] = 0;
}

__global__ void k_count(const int* __restrict__ ei) {
    int e = blockIdx.x * blockDim.x + threadIdx.x;
    if (e < NE) atomicAdd(&g_deg[ei[NE + e]], 1);
}

__global__ void __launch_bounds__(SCAN_B) k_scan1() {
    __shared__ int s[SCAN_B];
    int tid = threadIdx.x;
    int i = blockIdx.x * SCAN_B + tid;
    s[tid] = (i < NN) ? g_deg[i] : 0;
    __syncthreads();
#pragma unroll
    for (int off = 1; off < SCAN_B; off <<= 1) {
        int v = (tid >= off) ? s[tid - off] : 0;
        __syncthreads();
        s[tid] += v;
        __syncthreads();
    }
    if (i < NN) g_scan[i] = s[tid];
    if (tid == SCAN_B - 1) g_bsum[blockIdx.x] = s[tid];
}

__global__ void __launch_bounds__(128) k_scan2() {
    __shared__ int s[128];
    int t = threadIdx.x;
    int v = (t < NB_SCAN) ? g_bsum[t] : 0;
    s[t] = v;
    __syncthreads();
#pragma unroll
    for (int off = 1; off < 128; off <<= 1) {
        int u = (t >= off) ? s[t - off] : 0;
        __syncthreads();
        s[t] += u;
        __syncthreads();
    }
    if (t < NB_SCAN) g_boff[t] = s[t] - v;   // exclusive
}

__global__ void k_scan3() {
    int i = blockIdx.x * blockDim.x + threadIdx.x;
    if (i < NN) {
        int excl = g_scan[i] + g_boff[i >> 10] - g_deg[i];
        g_rowstart[i] = excl;
        g_cursor[i]   = excl;
        g_dis[i] = rsqrtf(1.0f + (float)g_deg[i]);
    }
}

__global__ void k_fill(const int* __restrict__ ei) {
    int e = blockIdx.x * blockDim.x + threadIdx.x;
    if (e < NE) {
        int s = ei[e];
        int d = ei[NE + e];
        int pos = atomicAdd(&g_cursor[d], 1);
        g_csrc[pos] = s;
    }
}

__global__ void k_gstart(const int* __restrict__ batch) {
    int i = blockIdx.x * blockDim.x + threadIdx.x;
    if (i <= NN) {
        int prev = (i == 0) ? -1 : batch[i - 1];
        int cur  = (i < NN) ? batch[i] : NG;
        for (int g = prev + 1; g <= cur; g++) g_gstart[g] = i;
    }
}

// ---------------------------------------------------------------------------
__device__ __forceinline__ float tf32_hi(float a) {
    return __uint_as_float(__float_as_uint(a) & 0xffffe000u);
}

// Precompute W mma fragments (one-time, shared by all GEMM blocks).
// Layout: [ks(16)][nt(16)][lane(32)] float4 = {b0hi, b1hi, b0lo, b1lo}
// lane(g,t): b0 = W[ks*8+t][nt*8+g], b1 = W[ks*8+t+4][nt*8+g]
__global__ void k_bfrag(const float* __restrict__ W, float4* __restrict__ out) {
    int i = blockIdx.x * blockDim.x + threadIdx.x;
    if (i >= 16 * 16 * 32) return;
    int lane = i & 31, nt = (i >> 5) & 15, ks = i >> 9;
    int g = lane >> 2, t = lane & 3;
    int n = nt * 8 + g;
    float b0 = W[(ks * 8 + t) * FD + n];
    float b1 = W[(ks * 8 + t + 4) * FD + n];
    float b0h = tf32_hi(b0), b1h = tf32_hi(b1);
    out[i] = make_float4(b0h, b1h, b0 - b0h, b1 - b1h);
}

__device__ __forceinline__ void mma_tf32(float4& d, float a0, float a1, float a2,
                                         float a3, float b0, float b1) {
    asm volatile(
        "mma.sync.aligned.m16n8k8.row.col.f32.tf32.tf32.f32 "
        "{%0,%1,%2,%3}, {%4,%5,%6,%7}, {%8,%9}, {%0,%1,%2,%3};\n"
        : "+f"(d.x), "+f"(d.y), "+f"(d.z), "+f"(d.w)
        : "r"(__float_as_uint(a0)), "r"(__float_as_uint(a1)),
          "r"(__float_as_uint(a2)), "r"(__float_as_uint(a3)),
          "r"(__float_as_uint(b0)), "r"(__float_as_uint(b1)));
}

// Zero-filling 16B async copy (src_size=0 -> fill with zeros).
__device__ __forceinline__ void cp_async16_z(float* smem, const float* gmem, int src_sz) {
    unsigned s = (unsigned)__cvta_generic_to_shared(smem);
    asm volatile("cp.async.cg.shared.global [%0], [%1], 16, %2;"
                 :: "r"(s), "l"(gmem), "r"(src_sz) : "memory");
}

// Tensor-core GEMM: Outh[NN,128](fp16) = f(A)[NN,128] @ W[128,128], split-TF32.
// Block 128x128, 256 threads, 2 blocks/SM. cp.async double-buffered A staging.
// Output quantized to fp16 (gather payload); accumulation stays fp32.
template <bool RELU_BIAS>
__global__ void __launch_bounds__(256, 2) k_gemm(
    const float* __restrict__ A, const float* __restrict__ bias,
    __half* __restrict__ Outh, const float4* __restrict__ Bfrag)
{
    __shared__ float sA[2][128 * 36];   // double-buffered A chunk (128 rows x 32 k)
    __shared__ float sBias[FD];

    const int block_row = blockIdx.x * 128;
    const int tid  = threadIdx.x;
    const int lane = tid & 31;
    const int w    = tid >> 5;
    const int rw   = w >> 1;        // warp row group (32 rows)
    const int cw   = w & 1;         // warp col half (64 cols)
    const int g    = lane >> 2, t = lane & 3;

    if (RELU_BIAS && tid < 32)
        *reinterpret_cast<float4*>(&sBias[tid * 4]) =
            *reinterpret_cast<const float4*>(&bias[tid * 4]);

    float4 acc0[8], acc1[8];
#pragma unroll
    for (int i = 0; i < 8; i++) {
        acc0[i] = make_float4(0.f, 0.f, 0.f, 0.f);
        acc1[i] = make_float4(0.f, 0.f, 0.f, 0.f);
    }

    // stage one 128x32 chunk into buffer (chunk&1) via cp.async
    auto stage = [&](int chunk) {
        const int k0c = chunk * 32;
        float* buf = sA[chunk & 1];
#pragma unroll
        for (int ii = 0; ii < 4; ii++) {
            int idx = tid + ii * 256;           // 1024 float4 total
            int r = idx >> 3, q = idx & 7;
            int row = block_row + r;
            const float* src = &A[(size_t)row * FD + k0c + q * 4];
            cp_async16_z(&buf[r * 36 + q * 4], src, row < NN ? 16 : 0);
        }
        asm volatile("cp.async.commit_group;" ::: "memory");
    };

    stage(0);
    stage(1);

#pragma unroll
    for (int chunk = 0; chunk < 4; chunk++) {
        if (chunk == 3) asm volatile("cp.async.wait_group 0;" ::: "memory");
        else            asm volatile("cp.async.wait_group 1;" ::: "memory");
        __syncthreads();

        const float* buf = sA[chunk & 1];
#pragma unroll
        for (int ksl = 0; ksl < 4; ksl++) {
            const int ks = chunk * 4 + ksl;
            const int c  = ksl * 8 + t;
            const int r0 = rw * 32 + g;
            // A fragments, both stripes (conflict-free: stride 36 mod 32 = 4)
            float a00 = buf[(r0     ) * 36 + c];
            float a01 = buf[(r0 +  8) * 36 + c];
            float a02 = buf[(r0     ) * 36 + c + 4];
            float a03 = buf[(r0 +  8) * 36 + c + 4];
            float a10 = buf[(r0 + 16) * 36 + c];
            float a11 = buf[(r0 + 24) * 36 + c];
            float a12 = buf[(r0 + 16) * 36 + c + 4];
            float a13 = buf[(r0 + 24) * 36 + c + 4];
            if (RELU_BIAS) {
                float b0v = sBias[chunk * 32 + c];
                float b1v = sBias[chunk * 32 + c + 4];
                a00 = fmaxf(a00 + b0v, 0.f); a01 = fmaxf(a01 + b0v, 0.f);
                a02 = fmaxf(a02 + b1v, 0.f); a03 = fmaxf(a03 + b1v, 0.f);
                a10 = fmaxf(a10 + b0v, 0.f); a11 = fmaxf(a11 + b0v, 0.f);
                a12 = fmaxf(a12 + b1v, 0.f); a13 = fmaxf(a13 + b1v, 0.f);
            }
            // register hi/lo split
            float h00 = tf32_hi(a00), h01 = tf32_hi(a01),
                  h02 = tf32_hi(a02), h03 = tf32_hi(a03);
            float h10 = tf32_hi(a10), h11 = tf32_hi(a11),
                  h12 = tf32_hi(a12), h13 = tf32_hi(a13);
            float l00 = a00 - h00, l01 = a01 - h01, l02 = a02 - h02, l03 = a03 - h03;
            float l10 = a10 - h10, l11 = a11 - h11, l12 = a12 - h12, l13 = a13 - h13;

            const float4* bp = &Bfrag[(ks * 16 + cw * 8) * 32 + lane];
#pragma unroll
            for (int nt8 = 0; nt8 < 8; nt8++) {
                float4 b = bp[nt8 * 32];
                // stripe 0: hi*hi, hi*lo, lo*hi
                mma_tf32(acc0[nt8], h00, h01, h02, h03, b.x, b.y);
                mma_tf32(acc0[nt8], h00, h01, h02, h03, b.z, b.w);
                mma_tf32(acc0[nt8], l00, l01, l02, l03, b.x, b.y);
                // stripe 1
                mma_tf32(acc1[nt8], h10, h11, h12, h13, b.x, b.y);
                mma_tf32(acc1[nt8], h10, h11, h12, h13, b.z, b.w);
                mma_tf32(acc1[nt8], l10, l11, l12, l13, b.x, b.y);
            }
        }
        __syncthreads();
        if (chunk + 2 < 4) stage(chunk + 2);
    }

    // epilogue (fp16): d0,d1 -> (row g, cols 2t,2t+1); d2,d3 -> row g+8
#pragma unroll
    for (int s = 0; s < 2; s++) {
        const float4* accs = s ? acc1 : acc0;
        int r0 = block_row + rw * 32 + s * 16 + g;
#pragma unroll
        for (int nt8 = 0; nt8 < 8; nt8++) {
            int col = cw * 64 + nt8 * 8 + t * 2;
            if (r0 < NN)
                *reinterpret_cast<__half2*>(&Outh[r0 * FD + col]) =
                    __float22half2_rn(make_float2(accs[nt8].x, accs[nt8].y));
            if (r0 + 8 < NN)
                *reinterpret_cast<__half2*>(&Outh[(r0 + 8) * FD + col]) =
                    __float22half2_rn(make_float2(accs[nt8].z, accs[nt8].w));
        }
    }
}

// ---------------------------------------------------------------------------
// CSR gather aggregation: warp per dst node, lane = 4 features (fp16 payload,
// 8B loads -> half the L2 traffic of fp32). Accumulation in fp32.
__device__ __forceinline__ float4 ld_hw4(const uint2* hw, int n, int lane) {
    uint2 raw = hw[n * 32 + lane];
    float2 f0 = __half22float2(*reinterpret_cast<__half2*>(&raw.x));
    float2 f1 = __half22float2(*reinterpret_cast<__half2*>(&raw.y));
    return make_float4(f0.x, f0.y, f1.x, f1.y);
}

__global__ void k_gather() {
    int gid = blockIdx.x * blockDim.x + threadIdx.x;
    int n = gid >> 5;
    int lane = gid & 31;
    if (n >= NN) return;

    const uint2* hw = reinterpret_cast<const uint2*>(g_hwh);
    int start = g_rowstart[n];
    int cnt   = g_deg[n];

    float4 acc = make_float4(0.f, 0.f, 0.f, 0.f);
    int j = 0;
    for (; j + 4 <= cnt; j += 4) {
        int s0 = g_csrc[start + j + 0];
        int s1 = g_csrc[start + j + 1];
        int s2 = g_csrc[start + j + 2];
        int s3 = g_csrc[start + j + 3];
        float w0 = g_dis[s0], w1 = g_dis[s1], w2 = g_dis[s2], w3 = g_dis[s3];
        float4 v0 = ld_hw4(hw, s0, lane);
        float4 v1 = ld_hw4(hw, s1, lane);
        float4 v2 = ld_hw4(hw, s2, lane);
        float4 v3 = ld_hw4(hw, s3, lane);
        acc.x += w0 * v0.x + w1 * v1.x + w2 * v2.x + w3 * v3.x;
        acc.y += w0 * v0.y + w1 * v1.y + w2 * v2.y + w3 * v3.y;
        acc.z += w0 * v0.z + w1 * v1.z + w2 * v2.z + w3 * v3.z;
        acc.w += w0 * v0.w + w1 * v1.w + w2 * v2.w + w3 * v3.w;
    }
    for (; j < cnt; j++) {
        int s = g_csrc[start + j];
        float w = g_dis[s];
        float4 v = ld_hw4(hw, s, lane);
        acc.x += w * v.x; acc.y += w * v.y;
        acc.z += w * v.z; acc.w += w * v.w;
    }
    float dd = g_dis[n];
    float w2s = dd * dd;
    float4 self = ld_hw4(hw, n, lane);
    float4 o = make_float4(dd * acc.x + w2s * self.x,
                           dd * acc.y + w2s * self.y,
                           dd * acc.z + w2s * self.z,
                           dd * acc.w + w2s * self.w);
    reinterpret_cast<float4*>(g_agg)[n * 32 + lane] = o;
}

// ---------------------------------------------------------------------------
// pooling over contiguous graph segments + readout, fused. Block per graph.
__global__ void __launch_bounds__(128) k_pool_final(
    const float* __restrict__ b2, const float* __restrict__ Wlin,
    const float* __restrict__ blin, float* __restrict__ out)
{
    __shared__ float sh[128];
    int g = blockIdx.x;
    int f = threadIdx.x;
    int n0 = g_gstart[g], n1 = g_gstart[g + 1];
    int cnt = n1 - n0;

    float acc = 0.0f;
#pragma unroll 4
    for (int n = n0; n < n1; n++) acc += g_agg[n * FD + f];

    float inv = (cnt > 0) ? 1.0f / (float)cnt : 0.0f;
    float pooled = acc * inv + ((cnt > 0) ? b2[f] : 0.0f);
    sh[f] = pooled * Wlin[f];
    __syncthreads();
#pragma unroll
    for (int off = 64; off > 0; off >>= 1) {
        if (f < off) sh[f] += sh[f + off];
        __syncthreads();
    }
    if (f == 0) out[g] = sh[0] + blin[0];
}

// ---------------------------------------------------------------------------
extern "C" void kernel_launch(void* const* d_in, const int* in_sizes, int n_in,
                              void* d_out, int out_size)
{
    const float* x     = (const float*)d_in[0];
    const int*   ei    = (const int*)d_in[1];     // int32
    const int*   batch = (const int*)d_in[2];     // int32
    const float* W1    = (const float*)d_in[3];
    const float* b1    = (const float*)d_in[4];
    const float* W2    = (const float*)d_in[5];
    const float* b2    = (const float*)d_in[6];
    const float* Wlin  = (const float*)d_in[7];
    const float* blin  = (const float*)d_in[8];
    float* out = (float*)d_out;

    void *p_hwh, *p_agg, *p_bf1, *p_bf2;
    cudaGetSymbolAddress(&p_hwh, g_hwh);
    cudaGetSymbolAddress(&p_agg, g_agg);
    cudaGetSymbolAddress(&p_bf1, g_bfrag1);
    cudaGetSymbolAddress(&p_bf2, g_bfrag2);
    __half* hwh = (__half*)p_hwh;
    float*  agg = (float*)p_agg;
    float4* bf1 = (float4*)p_bf1;
    float4* bf2 = (float4*)p_bf2;

    // Side stream + fork/join events (lazy one-time init; host-side objects,
    // created during the first non-captured correctness call).
    static cudaStream_t s2 = nullptr;
    static cudaEvent_t  eF = nullptr, eJ = nullptr;
    if (!s2) {
        cudaStreamCreateWithFlags(&s2, cudaStreamNonBlocking);
        cudaEventCreateWithFlags(&eF, cudaEventDisableTiming);
        cudaEventCreateWithFlags(&eJ, cudaEventDisableTiming);
    }

    const int T = 256;
    const int nn_blocks = (NN + T - 1) / T;
    const int ne_blocks = (NE + T - 1) / T;
    const int gemm_blocks = (NN + 127) / 128;
    const int gat_blocks = (NN * 32 + T - 1) / T;

    // Fork: CSR build + gstart + bfrag2 run on s2 concurrent with layer-1 GEMM
    // on the main (captured) stream. Join before gather1, which needs both.
    cudaEventRecord(eF, 0);
    cudaStreamWaitEvent(s2, eF, 0);

    k_zero       <<<nn_blocks, T, 0, s2>>>();
    k_count      <<<ne_blocks, T, 0, s2>>>(ei);
    k_bfrag      <<<32, 256>>>(W1, bf1);
    k_gemm<false><<<gemm_blocks, T>>>(x, nullptr, hwh, bf1);  // launch 3 (ncu slot)
    k_scan1      <<<NB_SCAN, SCAN_B, 0, s2>>>();
    k_scan2      <<<1, 128, 0, s2>>>();
    k_scan3      <<<nn_blocks, T, 0, s2>>>();
    k_fill       <<<ne_blocks, T, 0, s2>>>(ei);
    k_gstart     <<<(NN + 1 + T - 1) / T, T, 0, s2>>>(batch);
    k_bfrag      <<<32, 256, 0, s2>>>(W2, bf2);

    cudaEventRecord(eJ, s2);
    cudaStreamWaitEvent(0, eJ, 0);

    // Layer 1 aggregation, then layer 2 (main stream)
    k_gather     <<<gat_blocks, T>>>();
    k_gemm<true> <<<gemm_blocks, T>>>(agg, b1, hwh, bf2);
    k_gather     <<<gat_blocks, T>>>();

    // Mean-pool (contiguous segments) + readout, b2 folded with empty-graph guard
    k_pool_final <<<NG, 128>>>(b2, Wlin, blin, out);
}